// round 9
// baseline (speedup 1.0000x reference)
#include <cuda_runtime.h>
#include <cuda_fp16.h>
#include <math.h>
#include <stdint.h>

#define T_SEQ 4096
#define EMB   512
#define NHEAD 8
#define HDIM  64
#define QSCALE 0.18033688011112042f   // (1/8) * log2(e): softmax via ex2

// Scratch (allocation-free rule) — all fp16 intermediates
__device__ __align__(1024) __half g_x [T_SEQ * EMB];
__device__ __align__(1024) __half g_w [4 * EMB * EMB];
__device__ __align__(1024) __half g_Q [T_SEQ * EMB];
__device__ __align__(1024) __half g_K [T_SEQ * EMB];
__device__ __align__(1024) __half g_Vt[EMB * T_SEQ];   // [n=h*64+d][t]
__device__ __align__(1024) __half g_att[T_SEQ * EMB];

// ----------------------------------------------------------------- helpers
__device__ __forceinline__ uint32_t s2u(const void* p) {
    uint32_t a;
    asm("{ .reg .u64 t; cvta.to.shared.u64 t, %1; cvt.u32.u64 %0, t; }"
        : "=r"(a) : "l"(p));
    return a;
}
__device__ __forceinline__ uint32_t packh2(float lo, float hi) {
    __half2 h = __floats2half2_rn(lo, hi);
    return *(uint32_t*)&h;
}
__device__ __forceinline__ uint32_t ex2h2(uint32_t x) {
    uint32_t y;
    asm("ex2.approx.f16x2 %0, %1;" : "=r"(y) : "r"(x));
    return y;
}
__device__ __forceinline__ void ldsm4(uint32_t* r, uint32_t addr) {
    asm volatile("ldmatrix.sync.aligned.m8n8.x4.shared.b16 {%0,%1,%2,%3}, [%4];"
                 : "=r"(r[0]), "=r"(r[1]), "=r"(r[2]), "=r"(r[3]) : "r"(addr));
}
__device__ __forceinline__ void mma16(float* c, const uint32_t* a,
                                      uint32_t b0, uint32_t b1) {
    asm volatile(
        "mma.sync.aligned.m16n8k16.row.col.f32.f16.f16.f32 "
        "{%0,%1,%2,%3}, {%4,%5,%6,%7}, {%8,%9}, {%0,%1,%2,%3};"
        : "+f"(c[0]), "+f"(c[1]), "+f"(c[2]), "+f"(c[3])
        : "r"(a[0]), "r"(a[1]), "r"(a[2]), "r"(a[3]), "r"(b0), "r"(b1));
}
// 16B-chunk XOR swizzle (8 chunks per 128B row of 64 halves)
__device__ __forceinline__ uint32_t swz(uint32_t base, int rowBytes, int r, int kc) {
    return base + (uint32_t)r * rowBytes + ((uint32_t)(kc ^ (r & 7)) << 4);
}
__device__ __forceinline__ uint32_t fragAddr(uint32_t base, int rowBytes,
                                             int r0, int kc0, int lane) {
    int r  = r0 + (lane & 7) + ((lane >> 3) & 1) * 8;
    int kc = kc0 + (lane >> 4);
    return swz(base, rowBytes, r, kc);
}

#define CP16(dst, src)                                                          \
    asm volatile("{ .reg .u64 g; cvta.to.global.u64 g, %1;"                    \
                 " cp.async.cg.shared.global [%0], [g], 16; }"                  \
                 :: "r"(dst), "l"(src) : "memory")
#define CP_COMMIT()  asm volatile("cp.async.commit_group;" ::: "memory")
#define CP_WAITN(N)  asm volatile("cp.async.wait_group %0;" :: "n"(N) : "memory")

// ----------------------------------------------------------------- fused round
__global__ void round_all(const float* __restrict__ x,
                          const float* __restrict__ wq, const float* __restrict__ wk,
                          const float* __restrict__ wv, const float* __restrict__ wo,
                          __half* __restrict__ dx, __half* __restrict__ dw) {
    int i = blockIdx.x * 256 + threadIdx.x;          // 786432 float4 lanes
    const float4* src;
    __half* dstp;
    int off;
    if (i < 524288) {
        src = (const float4*)x; dstp = dx; off = i;
    } else {
        int j = i - 524288;
        int w = j >> 16;                             // 0..3
        off = j & 65535;
        const float* ws = (w == 0) ? wq : (w == 1) ? wk : (w == 2) ? wv : wo;
        src = (const float4*)ws;
        dstp = dw + (size_t)w * EMB * EMB;
    }
    float4 v = src[off];
    uint2 o = make_uint2(packh2(v.x, v.y), packh2(v.z, v.w));
    *((uint2*)dstp + off) = o;
}

// ----------------------------------------------------------------- GEMM core
// C[4096,512] = A[4096,512] @ B[512,512]^T, fp16 in / fp32 acc.
// BM=128 BN=64 BK=64, 256 thr. smem: A dbl 2x16K, B dbl 2x8K = 48K.
#define GSM 49152
__device__ __forceinline__ void gemm_body(const __half* A, const __half* B,
                                          void* Cout, float scale, int mode,
                                          int m0, int n0, char* sm) {
    const uint32_t sb = s2u(sm);
    const uint32_t sA[2] = {sb, sb + 16384};
    const uint32_t sB[2] = {sb + 32768, sb + 40960};

    const int tid = threadIdx.x, lane = tid & 31, wid = tid >> 5;
    const int wm = wid & 3, wn = wid >> 2;

    auto load = [&](int kt) {
        int buf = kt & 1;
#pragma unroll
        for (int p = 0; p < 4; p++) {
            int idx = p * 256 + tid, r = idx >> 3, kc = idx & 7;
            CP16(swz(sA[buf], 128, r, kc), &A[(size_t)(m0 + r) * EMB + kt * 64 + kc * 8]);
        }
#pragma unroll
        for (int p = 0; p < 2; p++) {
            int idx = p * 256 + tid, r = idx >> 3, kc = idx & 7;
            CP16(swz(sB[buf], 128, r, kc), &B[(size_t)(n0 + r) * EMB + kt * 64 + kc * 8]);
        }
    };

    float acc[2][4][4] = {};
    load(0); CP_COMMIT();

    for (int kt = 0; kt < 8; kt++) {
        if (kt < 7) { load(kt + 1); CP_COMMIT(); CP_WAITN(1); }
        else        { CP_WAITN(0); }
        __syncthreads();
        const uint32_t a0 = sA[kt & 1], b0 = sB[kt & 1];
#pragma unroll
        for (int s = 0; s < 4; s++) {               // k16 steps
            uint32_t af[2][4], bf[2][4];
#pragma unroll
            for (int mf = 0; mf < 2; mf++)
                ldsm4(af[mf], fragAddr(a0, 128, wm * 32 + mf * 16, s * 2, lane));
#pragma unroll
            for (int p = 0; p < 2; p++)
                ldsm4(bf[p], fragAddr(b0, 128, wn * 32 + p * 16, s * 2, lane));
#pragma unroll
            for (int mf = 0; mf < 2; mf++)
#pragma unroll
                for (int p = 0; p < 2; p++) {
                    mma16(acc[mf][2 * p],     af[mf], bf[p][0], bf[p][2]);
                    mma16(acc[mf][2 * p + 1], af[mf], bf[p][1], bf[p][3]);
                }
        }
        __syncthreads();
    }

#pragma unroll
    for (int mf = 0; mf < 2; mf++) {
        int r0 = m0 + wm * 32 + mf * 16 + (lane >> 2);
#pragma unroll
        for (int nf = 0; nf < 4; nf++) {
            int col = n0 + wn * 32 + nf * 8 + 2 * (lane & 3);
            float v0 = acc[mf][nf][0] * scale, v1 = acc[mf][nf][1] * scale;
            float v2 = acc[mf][nf][2] * scale, v3 = acc[mf][nf][3] * scale;
            if (mode == 0) {                         // half, row-major
                __half* C = (__half*)Cout;
                *(uint32_t*)&C[(size_t)r0 * EMB + col]       = packh2(v0, v1);
                *(uint32_t*)&C[(size_t)(r0 + 8) * EMB + col] = packh2(v2, v3);
            } else if (mode == 1) {                  // half, transposed (Vt)
                __half* C = (__half*)Cout;
                C[(size_t)col * T_SEQ + r0]           = __float2half_rn(v0);
                C[(size_t)(col + 1) * T_SEQ + r0]     = __float2half_rn(v1);
                C[(size_t)col * T_SEQ + r0 + 8]       = __float2half_rn(v2);
                C[(size_t)(col + 1) * T_SEQ + r0 + 8] = __float2half_rn(v3);
            } else {                                 // fp32 final output
                float* C = (float*)Cout;
                *(float2*)&C[(size_t)r0 * EMB + col]       = make_float2(v0, v1);
                *(float2*)&C[(size_t)(r0 + 8) * EMB + col] = make_float2(v2, v3);
            }
        }
    }
}

// Fused QKV: blockIdx.x: [0,8) -> Q, [8,16) -> K, [16,24) -> V(transposed out)
__global__ __launch_bounds__(256, 2) void qkv_gemm(const __half* __restrict__ A,
                                                   const __half* __restrict__ W,
                                                   __half* __restrict__ Cq,
                                                   __half* __restrict__ Ck,
                                                   __half* __restrict__ Cv) {
    extern __shared__ __align__(1024) char sm[];
    int which = blockIdx.x >> 3;
    int n0 = (blockIdx.x & 7) * 64;
    int m0 = blockIdx.y * 128;
    const __half* B = W + (size_t)which * EMB * EMB;
    __half* C = (which == 0) ? Cq : (which == 1) ? Ck : Cv;
    float scale = (which == 0) ? QSCALE : 1.0f;
    gemm_body(A, B, C, scale, (which == 2) ? 1 : 0, m0, n0, sm);
}

__global__ __launch_bounds__(256, 2) void gemm_out(const __half* __restrict__ A,
                                                   const __half* __restrict__ B,
                                                   float* __restrict__ C) {
    extern __shared__ __align__(1024) char sm[];
    gemm_body(A, B, C, 1.0f, 2, blockIdx.y * 128, blockIdx.x * 64, sm);
}

// ----------------------------------------------------------------- attention
// CTA: 256 q x 1 head, 64 key tiles of 64 keys, 256 thr, 1 CTA/SM (high regs).
// Warp owns 32 q-rows across ALL keys. exp via ex2.approx.f16x2 (output IS the
// packed fp16 A-frag). l = P x ones via one extra MMA per k16 chunk (exactly
// consistent with the P the PV-MMA consumes). K and V double-buffered.
// smem: Q 32K | K dbl 16K | V dbl 16K = 64K. Grid 16x8 = 128 CTAs, one wave.
#define ASMEM 65536
#define ONESH2 0x3C003C00u
__global__ __launch_bounds__(256, 1) void attn_tc(const __half* __restrict__ Q,
                                                  const __half* __restrict__ K,
                                                  const __half* __restrict__ Vt,
                                                  __half* __restrict__ O) {
    extern __shared__ __align__(1024) char sm[];
    const uint32_t sb = s2u(sm);
    const uint32_t sQ = sb;
    const uint32_t sK[2] = {sb + 32768, sb + 40960};
    const uint32_t sV[2] = {sb + 49152, sb + 57344};

    const int tid = threadIdx.x, lane = tid & 31, wid = tid >> 5;
    const int h = blockIdx.y, q0 = blockIdx.x * 256;

    auto loadK = [&](int t) {
        int k0 = t * 64;
        uint32_t base = sK[t & 1];
#pragma unroll
        for (int p = 0; p < 2; p++) {
            int idx = p * 256 + tid, r = idx >> 3, kc = idx & 7;
            CP16(swz(base, 128, r, kc), &K[(size_t)(k0 + r) * EMB + h * HDIM + kc * 8]);
        }
    };
    auto loadV = [&](int t) {
        uint32_t base = sV[t & 1];
#pragma unroll
        for (int p = 0; p < 2; p++) {
            int idx = p * 256 + tid, r = idx >> 3, kc = idx & 7;
            CP16(swz(base, 128, r, kc), &Vt[(size_t)(h * HDIM + r) * T_SEQ + t * 64 + kc * 8]);
        }
    };

    // prologue: {Q(256 rows, 32KB), K0} group, {V0} group
#pragma unroll
    for (int p = 0; p < 8; p++) {
        int idx = p * 256 + tid, r = idx >> 3, kc = idx & 7;
        CP16(swz(sQ, 128, r, kc), &Q[(size_t)(q0 + r) * EMB + h * HDIM + kc * 8]);
    }
    loadK(0); CP_COMMIT();
    loadV(0); CP_COMMIT();
    CP_WAITN(1);               // Q, K0 resident
    __syncthreads();

    // register-cache Q fragments: m32 x k64 per warp = 32 regs
    uint32_t qf[4][2][4];
#pragma unroll
    for (int s = 0; s < 4; s++)
#pragma unroll
        for (int mf = 0; mf < 2; mf++)
            ldsm4(qf[s][mf], fragAddr(sQ, 128, wid * 32 + mf * 16, s * 2, lane));

    float oacc[2][8][4] = {};
    float lacc[2][4] = {};

    for (int t = 0; t < 64; t++) {
        if (t < 63) {
            loadK(t + 1); CP_COMMIT();
            loadV(t + 1); CP_COMMIT();
            CP_WAITN(2);       // K(t), V(t) resident
        } else {
            CP_WAITN(0);
        }
        __syncthreads();

        // --- S = Q K(t)^T over all 64 keys (log2 domain) ---
        float sacc[2][8][4] = {};
        const uint32_t kb = sK[t & 1];
#pragma unroll
        for (int s = 0; s < 4; s++) {
            uint32_t kf[4][4];
#pragma unroll
            for (int nb = 0; nb < 4; nb++)
                ldsm4(kf[nb], fragAddr(kb, 128, nb * 16, s * 2, lane));
#pragma unroll
            for (int mf = 0; mf < 2; mf++)
#pragma unroll
                for (int nb = 0; nb < 4; nb++) {
                    mma16(sacc[mf][2 * nb],     qf[s][mf], kf[nb][0], kf[nb][2]);
                    mma16(sacc[mf][2 * nb + 1], qf[s][mf], kf[nb][1], kf[nb][3]);
                }
        }

        // --- P = 2^S via f16x2 MUFU (output = packed A-frag); l via ones-MMA ---
        uint32_t aP[2][4][4];
#pragma unroll
        for (int mf = 0; mf < 2; mf++) {
#pragma unroll
            for (int nf = 0; nf < 8; nf++) {
                uint32_t e01 = ex2h2(packh2(sacc[mf][nf][0], sacc[mf][nf][1]));
                uint32_t e23 = ex2h2(packh2(sacc[mf][nf][2], sacc[mf][nf][3]));
                int ks = nf >> 1, hi = (nf & 1) * 2;
                aP[mf][ks][hi]     = e01;
                aP[mf][ks][hi + 1] = e23;
            }
#pragma unroll
            for (int ks = 0; ks < 4; ks++)
                mma16(lacc[mf], aP[mf][ks], ONESH2, ONESH2);
        }

        // --- O += P V(t) over all 64 keys ---
        const uint32_t vb = sV[t & 1];
#pragma unroll
        for (int ks = 0; ks < 4; ks++) {
            uint32_t bf[4][4];
#pragma unroll
            for (int p = 0; p < 4; p++)
                ldsm4(bf[p], fragAddr(vb, 128, p * 16, ks * 2, lane));
#pragma unroll
            for (int mf = 0; mf < 2; mf++)
#pragma unroll
                for (int p = 0; p < 4; p++) {
                    mma16(oacc[mf][2 * p],     aP[mf][ks], bf[p][0], bf[p][2]);
                    mma16(oacc[mf][2 * p + 1], aP[mf][ks], bf[p][1], bf[p][3]);
                }
        }
        __syncthreads();       // K/V buffer reuse safe
    }

    // --- O /= l (l from ones-MMA: rows r / r+8 in lacc[mf][0] / [2]) ---
#pragma unroll
    for (int mf = 0; mf < 2; mf++) {
        float li0 = 1.0f / lacc[mf][0];
        float li1 = 1.0f / lacc[mf][2];
        int r = wid * 32 + mf * 16 + (lane >> 2);
#pragma unroll
        for (int df = 0; df < 8; df++) {
            int col = df * 8 + 2 * (lane & 3);
            *(uint32_t*)&O[(size_t)(q0 + r) * EMB + h * HDIM + col] =
                packh2(oacc[mf][df][0] * li0, oacc[mf][df][1] * li0);
            *(uint32_t*)&O[(size_t)(q0 + r + 8) * EMB + h * HDIM + col] =
                packh2(oacc[mf][df][2] * li1, oacc[mf][df][3] * li1);
        }
    }
}

// ----------------------------------------------------------------- launch
extern "C" void kernel_launch(void* const* d_in, const int* in_sizes, int n_in,
                              void* d_out, int out_size) {
    const float* x  = (const float*)d_in[0];
    const float* wq = (const float*)d_in[1];
    const float* wk = (const float*)d_in[2];
    const float* wv = (const float*)d_in[3];
    const float* wo = (const float*)d_in[4];
    float* out = (float*)d_out;

    __half *px, *pw, *pQ, *pK, *pVt, *pA;
    cudaGetSymbolAddress((void**)&px, g_x);
    cudaGetSymbolAddress((void**)&pw, g_w);
    cudaGetSymbolAddress((void**)&pQ, g_Q);
    cudaGetSymbolAddress((void**)&pK, g_K);
    cudaGetSymbolAddress((void**)&pVt, g_Vt);
    cudaGetSymbolAddress((void**)&pA, g_att);

    cudaFuncSetAttribute(qkv_gemm, cudaFuncAttributeMaxDynamicSharedMemorySize, GSM);
    cudaFuncSetAttribute(gemm_out, cudaFuncAttributeMaxDynamicSharedMemorySize, GSM);
    cudaFuncSetAttribute(attn_tc, cudaFuncAttributeMaxDynamicSharedMemorySize, ASMEM);

    round_all<<<3072, 256>>>(x, wq, wk, wv, wo, px, pw);

    qkv_gemm<<<dim3(24, 32), 256, GSM>>>(px, pw, pQ, pK, pVt);

    dim3 ga(T_SEQ / 256, NHEAD);       // (16, 8) = 128 CTAs, one wave
    attn_tc<<<ga, 256, ASMEM>>>(pQ, pK, pVt, pA);

    gemm_out<<<dim3(8, 32), 256, GSM>>>(pA, pw + 3 * (size_t)EMB * EMB, out);
}

// round 10
// speedup vs baseline: 1.0145x; 1.0145x over previous
#include <cuda_runtime.h>
#include <cuda_fp16.h>
#include <math.h>
#include <stdint.h>

#define T_SEQ 4096
#define EMB   512
#define NHEAD 8
#define HDIM  64
#define QSCALE 0.18033688011112042f   // (1/8) * log2(e): softmax via ex2

// Scratch (allocation-free rule) — all fp16 intermediates
__device__ __align__(1024) __half g_x [T_SEQ * EMB];
__device__ __align__(1024) __half g_w [4 * EMB * EMB];
__device__ __align__(1024) __half g_Q [T_SEQ * EMB];
__device__ __align__(1024) __half g_K [T_SEQ * EMB];
__device__ __align__(1024) __half g_Vt[EMB * T_SEQ];   // [n=h*64+d][t]
__device__ __align__(1024) __half g_att[T_SEQ * EMB];

// ----------------------------------------------------------------- helpers
__device__ __forceinline__ uint32_t s2u(const void* p) {
    uint32_t a;
    asm("{ .reg .u64 t; cvta.to.shared.u64 t, %1; cvt.u32.u64 %0, t; }"
        : "=r"(a) : "l"(p));
    return a;
}
__device__ __forceinline__ uint32_t packh2(float lo, float hi) {
    __half2 h = __floats2half2_rn(lo, hi);
    return *(uint32_t*)&h;
}
__device__ __forceinline__ uint32_t ex2h2(uint32_t x) {
    uint32_t y;
    asm("ex2.approx.f16x2 %0, %1;" : "=r"(y) : "r"(x));
    return y;
}
__device__ __forceinline__ void ldsm4(uint32_t* r, uint32_t addr) {
    asm volatile("ldmatrix.sync.aligned.m8n8.x4.shared.b16 {%0,%1,%2,%3}, [%4];"
                 : "=r"(r[0]), "=r"(r[1]), "=r"(r[2]), "=r"(r[3]) : "r"(addr));
}
__device__ __forceinline__ void mma16(float* c, const uint32_t* a,
                                      uint32_t b0, uint32_t b1) {
    asm volatile(
        "mma.sync.aligned.m16n8k16.row.col.f32.f16.f16.f32 "
        "{%0,%1,%2,%3}, {%4,%5,%6,%7}, {%8,%9}, {%0,%1,%2,%3};"
        : "+f"(c[0]), "+f"(c[1]), "+f"(c[2]), "+f"(c[3])
        : "r"(a[0]), "r"(a[1]), "r"(a[2]), "r"(a[3]), "r"(b0), "r"(b1));
}
// 16B-chunk XOR swizzle (8 chunks per 128B row of 64 halves)
__device__ __forceinline__ uint32_t swz(uint32_t base, int rowBytes, int r, int kc) {
    return base + (uint32_t)r * rowBytes + ((uint32_t)(kc ^ (r & 7)) << 4);
}
__device__ __forceinline__ uint32_t fragAddr(uint32_t base, int rowBytes,
                                             int r0, int kc0, int lane) {
    int r  = r0 + (lane & 7) + ((lane >> 3) & 1) * 8;
    int kc = kc0 + (lane >> 4);
    return swz(base, rowBytes, r, kc);
}

#define CP16(dst, src)                                                          \
    asm volatile("{ .reg .u64 g; cvta.to.global.u64 g, %1;"                    \
                 " cp.async.cg.shared.global [%0], [g], 16; }"                  \
                 :: "r"(dst), "l"(src) : "memory")
#define CP_COMMIT()  asm volatile("cp.async.commit_group;" ::: "memory")
#define CP_WAITN(N)  asm volatile("cp.async.wait_group %0;" :: "n"(N) : "memory")

// ----------------------------------------------------------------- fused round
__global__ void round_all(const float* __restrict__ x,
                          const float* __restrict__ wq, const float* __restrict__ wk,
                          const float* __restrict__ wv, const float* __restrict__ wo,
                          __half* __restrict__ dx, __half* __restrict__ dw) {
    int i = blockIdx.x * 256 + threadIdx.x;          // 786432 float4 lanes
    const float4* src;
    __half* dstp;
    int off;
    if (i < 524288) {
        src = (const float4*)x; dstp = dx; off = i;
    } else {
        int j = i - 524288;
        int w = j >> 16;                             // 0..3
        off = j & 65535;
        const float* ws = (w == 0) ? wq : (w == 1) ? wk : (w == 2) ? wv : wo;
        src = (const float4*)ws;
        dstp = dw + (size_t)w * EMB * EMB;
    }
    float4 v = src[off];
    uint2 o = make_uint2(packh2(v.x, v.y), packh2(v.z, v.w));
    *((uint2*)dstp + off) = o;
}

// ----------------------------------------------------------------- GEMM core
// C[4096,512] = A[4096,512] @ B[512,512]^T, fp16 in / fp32 acc.
// BM=128 BN=64 BK=64, 256 thr. smem: A dbl 2x16K, B dbl 2x8K = 48K.
#define GSM 49152
__device__ __forceinline__ void gemm_body(const __half* A, const __half* B,
                                          void* Cout, float scale, int mode,
                                          int m0, int n0, char* sm) {
    const uint32_t sb = s2u(sm);
    const uint32_t sA[2] = {sb, sb + 16384};
    const uint32_t sB[2] = {sb + 32768, sb + 40960};

    const int tid = threadIdx.x, lane = tid & 31, wid = tid >> 5;
    const int wm = wid & 3, wn = wid >> 2;

    auto load = [&](int kt) {
        int buf = kt & 1;
#pragma unroll
        for (int p = 0; p < 4; p++) {
            int idx = p * 256 + tid, r = idx >> 3, kc = idx & 7;
            CP16(swz(sA[buf], 128, r, kc), &A[(size_t)(m0 + r) * EMB + kt * 64 + kc * 8]);
        }
#pragma unroll
        for (int p = 0; p < 2; p++) {
            int idx = p * 256 + tid, r = idx >> 3, kc = idx & 7;
            CP16(swz(sB[buf], 128, r, kc), &B[(size_t)(n0 + r) * EMB + kt * 64 + kc * 8]);
        }
    };

    float acc[2][4][4] = {};
    load(0); CP_COMMIT();

    for (int kt = 0; kt < 8; kt++) {
        if (kt < 7) { load(kt + 1); CP_COMMIT(); CP_WAITN(1); }
        else        { CP_WAITN(0); }
        __syncthreads();
        const uint32_t a0 = sA[kt & 1], b0 = sB[kt & 1];
#pragma unroll
        for (int s = 0; s < 4; s++) {               // k16 steps
            uint32_t af[2][4], bf[2][4];
#pragma unroll
            for (int mf = 0; mf < 2; mf++)
                ldsm4(af[mf], fragAddr(a0, 128, wm * 32 + mf * 16, s * 2, lane));
#pragma unroll
            for (int p = 0; p < 2; p++)
                ldsm4(bf[p], fragAddr(b0, 128, wn * 32 + p * 16, s * 2, lane));
#pragma unroll
            for (int mf = 0; mf < 2; mf++)
#pragma unroll
                for (int p = 0; p < 2; p++) {
                    mma16(acc[mf][2 * p],     af[mf], bf[p][0], bf[p][2]);
                    mma16(acc[mf][2 * p + 1], af[mf], bf[p][1], bf[p][3]);
                }
        }
        __syncthreads();
    }

#pragma unroll
    for (int mf = 0; mf < 2; mf++) {
        int r0 = m0 + wm * 32 + mf * 16 + (lane >> 2);
#pragma unroll
        for (int nf = 0; nf < 4; nf++) {
            int col = n0 + wn * 32 + nf * 8 + 2 * (lane & 3);
            float v0 = acc[mf][nf][0] * scale, v1 = acc[mf][nf][1] * scale;
            float v2 = acc[mf][nf][2] * scale, v3 = acc[mf][nf][3] * scale;
            if (mode == 0) {                         // half, row-major
                __half* C = (__half*)Cout;
                *(uint32_t*)&C[(size_t)r0 * EMB + col]       = packh2(v0, v1);
                *(uint32_t*)&C[(size_t)(r0 + 8) * EMB + col] = packh2(v2, v3);
            } else if (mode == 1) {                  // half, transposed (Vt)
                __half* C = (__half*)Cout;
                C[(size_t)col * T_SEQ + r0]           = __float2half_rn(v0);
                C[(size_t)(col + 1) * T_SEQ + r0]     = __float2half_rn(v1);
                C[(size_t)col * T_SEQ + r0 + 8]       = __float2half_rn(v2);
                C[(size_t)(col + 1) * T_SEQ + r0 + 8] = __float2half_rn(v3);
            } else {                                 // fp32 final output
                float* C = (float*)Cout;
                *(float2*)&C[(size_t)r0 * EMB + col]       = make_float2(v0, v1);
                *(float2*)&C[(size_t)(r0 + 8) * EMB + col] = make_float2(v2, v3);
            }
        }
    }
}

// Fused QKV: blockIdx.x: [0,8) -> Q, [8,16) -> K, [16,24) -> V(transposed out)
__global__ __launch_bounds__(256, 2) void qkv_gemm(const __half* __restrict__ A,
                                                   const __half* __restrict__ W,
                                                   __half* __restrict__ Cq,
                                                   __half* __restrict__ Ck,
                                                   __half* __restrict__ Cv) {
    extern __shared__ __align__(1024) char sm[];
    int which = blockIdx.x >> 3;
    int n0 = (blockIdx.x & 7) * 64;
    int m0 = blockIdx.y * 128;
    const __half* B = W + (size_t)which * EMB * EMB;
    __half* C = (which == 0) ? Cq : (which == 1) ? Ck : Cv;
    float scale = (which == 0) ? QSCALE : 1.0f;
    gemm_body(A, B, C, scale, (which == 2) ? 1 : 0, m0, n0, sm);
}

__global__ __launch_bounds__(256, 2) void gemm_out(const __half* __restrict__ A,
                                                   const __half* __restrict__ B,
                                                   float* __restrict__ C) {
    extern __shared__ __align__(1024) char sm[];
    gemm_body(A, B, C, 1.0f, 2, blockIdx.y * 128, blockIdx.x * 64, sm);
}

// ----------------------------------------------------------------- attention
// CTA: 128 q x 1 head, 64 key tiles of 64 keys, 256 thr, 2 CTAs/SM.
// Warp owns 16 q-rows across ALL keys (no cross-warp reduce). exp via
// ex2.approx.f16x2 (output = packed fp16 A-frag). l = P x ones via one extra
// MMA per k16 chunk. K and V TRIPLE-buffered (prefetch 2 tiles ahead) so the
// per-tile cp.async wait is a no-op. smem: Q 16K | K 3x8K | V 3x8K = 64K.
#define ASMEM 65536
#define ONESH2 0x3C003C00u
__global__ __launch_bounds__(256, 2) void attn_tc(const __half* __restrict__ Q,
                                                  const __half* __restrict__ K,
                                                  const __half* __restrict__ Vt,
                                                  __half* __restrict__ O) {
    extern __shared__ __align__(1024) char sm[];
    const uint32_t sb = s2u(sm);
    const uint32_t sQ = sb;
    const uint32_t sK[3] = {sb + 16384, sb + 24576, sb + 32768};
    const uint32_t sV[3] = {sb + 40960, sb + 49152, sb + 57344};

    const int tid = threadIdx.x, lane = tid & 31, wid = tid >> 5;
    const int h = blockIdx.y, q0 = blockIdx.x * 128;

    auto loadKV = [&](int t, int buf) {
        int k0 = t * 64;
#pragma unroll
        for (int p = 0; p < 2; p++) {
            int idx = p * 256 + tid, r = idx >> 3, kc = idx & 7;
            CP16(swz(sK[buf], 128, r, kc), &K[(size_t)(k0 + r) * EMB + h * HDIM + kc * 8]);
            CP16(swz(sV[buf], 128, r, kc), &Vt[(size_t)(h * HDIM + r) * T_SEQ + k0 + kc * 8]);
        }
    };

    // prologue: group0 = {Q, K0, V0}, group1 = {K1, V1}
#pragma unroll
    for (int p = 0; p < 4; p++) {
        int idx = p * 256 + tid, r = idx >> 3, kc = idx & 7;
        CP16(swz(sQ, 128, r, kc), &Q[(size_t)(q0 + r) * EMB + h * HDIM + kc * 8]);
    }
    loadKV(0, 0); CP_COMMIT();
    loadKV(1, 1); CP_COMMIT();
    CP_WAITN(1);               // Q, K0, V0 resident
    __syncthreads();

    // register-cache Q fragments: m16 x k64 per warp = 16 regs
    uint32_t qf[4][4];
#pragma unroll
    for (int s = 0; s < 4; s++)
        ldsm4(qf[s], fragAddr(sQ, 128, wid * 16, s * 2, lane));

    float oacc[8][4] = {};
    float lacc[4] = {};

    int buf = 0;               // buffer of tile t (t % 3)
    for (int t = 0; t < 64; t++) {
        // issue prefetch for t+2 into buffer (t+2)%3 == (buf+2)%3
        if (t + 2 < 64) {
            int pb = buf + 2; if (pb >= 3) pb -= 3;
            loadKV(t + 2, pb);
        }
        CP_COMMIT();
        CP_WAITN(2);           // groups through tile t complete (usually no-op)
        __syncthreads();

        // --- S = Q K(t)^T over all 64 keys (log2 domain) ---
        float sacc[8][4] = {};
        const uint32_t kb = sK[buf];
#pragma unroll
        for (int s = 0; s < 4; s++) {
            uint32_t kf[4][4];
#pragma unroll
            for (int nb = 0; nb < 4; nb++)
                ldsm4(kf[nb], fragAddr(kb, 128, nb * 16, s * 2, lane));
#pragma unroll
            for (int nb = 0; nb < 4; nb++) {
                mma16(sacc[2 * nb],     qf[s], kf[nb][0], kf[nb][2]);
                mma16(sacc[2 * nb + 1], qf[s], kf[nb][1], kf[nb][3]);
            }
        }

        // --- P = 2^S via f16x2 MUFU (output = packed A-frag); l via ones-MMA ---
        uint32_t aP[4][4];
#pragma unroll
        for (int nf = 0; nf < 8; nf++) {
            uint32_t e01 = ex2h2(packh2(sacc[nf][0], sacc[nf][1]));
            uint32_t e23 = ex2h2(packh2(sacc[nf][2], sacc[nf][3]));
            int ks = nf >> 1, hi = (nf & 1) * 2;
            aP[ks][hi]     = e01;
            aP[ks][hi + 1] = e23;
        }
#pragma unroll
        for (int ks = 0; ks < 4; ks++)
            mma16(lacc, aP[ks], ONESH2, ONESH2);

        // --- O += P V(t) over all 64 keys ---
        const uint32_t vb = sV[buf];
#pragma unroll
        for (int ks = 0; ks < 4; ks++) {
            uint32_t bf[4][4];
#pragma unroll
            for (int p = 0; p < 4; p++)
                ldsm4(bf[p], fragAddr(vb, 128, p * 16, ks * 2, lane));
#pragma unroll
            for (int p = 0; p < 4; p++) {
                mma16(oacc[2 * p],     aP[ks], bf[p][0], bf[p][2]);
                mma16(oacc[2 * p + 1], aP[ks], bf[p][1], bf[p][3]);
            }
        }
        __syncthreads();       // all warps done with tile t-? buffer reuse safe
        buf++; if (buf >= 3) buf = 0;
    }

    // --- O /= l (l from ones-MMA: rows r / r+8 in lacc[0] / lacc[2]) ---
    float li0 = 1.0f / lacc[0];
    float li1 = 1.0f / lacc[2];
    int r = wid * 16 + (lane >> 2);
#pragma unroll
    for (int df = 0; df < 8; df++) {
        int col = df * 8 + 2 * (lane & 3);
        *(uint32_t*)&O[(size_t)(q0 + r) * EMB + h * HDIM + col] =
            packh2(oacc[df][0] * li0, oacc[df][1] * li0);
        *(uint32_t*)&O[(size_t)(q0 + r + 8) * EMB + h * HDIM + col] =
            packh2(oacc[df][2] * li1, oacc[df][3] * li1);
    }
}

// ----------------------------------------------------------------- launch
extern "C" void kernel_launch(void* const* d_in, const int* in_sizes, int n_in,
                              void* d_out, int out_size) {
    const float* x  = (const float*)d_in[0];
    const float* wq = (const float*)d_in[1];
    const float* wk = (const float*)d_in[2];
    const float* wv = (const float*)d_in[3];
    const float* wo = (const float*)d_in[4];
    float* out = (float*)d_out;

    __half *px, *pw, *pQ, *pK, *pVt, *pA;
    cudaGetSymbolAddress((void**)&px, g_x);
    cudaGetSymbolAddress((void**)&pw, g_w);
    cudaGetSymbolAddress((void**)&pQ, g_Q);
    cudaGetSymbolAddress((void**)&pK, g_K);
    cudaGetSymbolAddress((void**)&pVt, g_Vt);
    cudaGetSymbolAddress((void**)&pA, g_att);

    cudaFuncSetAttribute(qkv_gemm, cudaFuncAttributeMaxDynamicSharedMemorySize, GSM);
    cudaFuncSetAttribute(gemm_out, cudaFuncAttributeMaxDynamicSharedMemorySize, GSM);
    cudaFuncSetAttribute(attn_tc, cudaFuncAttributeMaxDynamicSharedMemorySize, ASMEM);

    round_all<<<3072, 256>>>(x, wq, wk, wv, wo, px, pw);

    qkv_gemm<<<dim3(24, 32), 256, GSM>>>(px, pw, pQ, pK, pVt);

    dim3 ga(T_SEQ / 128, NHEAD);       // (32, 8) = 256 CTAs, one wave @2/SM
    attn_tc<<<ga, 256, ASMEM>>>(pQ, pK, pVt, pA);

    gemm_out<<<dim3(8, 32), 256, GSM>>>(pA, pw + 3 * (size_t)EMB * EMB, out);
}

// round 11
// speedup vs baseline: 1.0235x; 1.0089x over previous
#include <cuda_runtime.h>
#include <cuda_fp16.h>
#include <math.h>
#include <stdint.h>

#define T_SEQ 4096
#define EMB   512
#define NHEAD 8
#define HDIM  64
#define QSCALE 0.18033688011112042f   // (1/8) * log2(e): softmax via ex2

// Scratch (allocation-free rule) — all fp16 intermediates
__device__ __align__(1024) __half g_x [T_SEQ * EMB];
__device__ __align__(1024) __half g_w [4 * EMB * EMB];
__device__ __align__(1024) __half g_Q [T_SEQ * EMB];
__device__ __align__(1024) __half g_K [T_SEQ * EMB];
__device__ __align__(1024) __half g_Vt[EMB * T_SEQ];   // [n=h*64+d][t]
__device__ __align__(1024) __half g_att[T_SEQ * EMB];

// ----------------------------------------------------------------- helpers
__device__ __forceinline__ uint32_t s2u(const void* p) {
    uint32_t a;
    asm("{ .reg .u64 t; cvta.to.shared.u64 t, %1; cvt.u32.u64 %0, t; }"
        : "=r"(a) : "l"(p));
    return a;
}
__device__ __forceinline__ uint32_t packh2(float lo, float hi) {
    __half2 h = __floats2half2_rn(lo, hi);
    return *(uint32_t*)&h;
}
__device__ __forceinline__ uint32_t ex2h2(uint32_t x) {
    uint32_t y;
    asm("ex2.approx.f16x2 %0, %1;" : "=r"(y) : "r"(x));
    return y;
}
__device__ __forceinline__ void ldsm4(uint32_t* r, uint32_t addr) {
    asm volatile("ldmatrix.sync.aligned.m8n8.x4.shared.b16 {%0,%1,%2,%3}, [%4];"
                 : "=r"(r[0]), "=r"(r[1]), "=r"(r[2]), "=r"(r[3]) : "r"(addr));
}
__device__ __forceinline__ void mma16(float* c, const uint32_t* a,
                                      uint32_t b0, uint32_t b1) {
    asm volatile(
        "mma.sync.aligned.m16n8k16.row.col.f32.f16.f16.f32 "
        "{%0,%1,%2,%3}, {%4,%5,%6,%7}, {%8,%9}, {%0,%1,%2,%3};"
        : "+f"(c[0]), "+f"(c[1]), "+f"(c[2]), "+f"(c[3])
        : "r"(a[0]), "r"(a[1]), "r"(a[2]), "r"(a[3]), "r"(b0), "r"(b1));
}
// 16B-chunk XOR swizzle (8 chunks per 128B row of 64 halves)
__device__ __forceinline__ uint32_t swz(uint32_t base, int rowBytes, int r, int kc) {
    return base + (uint32_t)r * rowBytes + ((uint32_t)(kc ^ (r & 7)) << 4);
}
__device__ __forceinline__ uint32_t fragAddr(uint32_t base, int rowBytes,
                                             int r0, int kc0, int lane) {
    int r  = r0 + (lane & 7) + ((lane >> 3) & 1) * 8;
    int kc = kc0 + (lane >> 4);
    return swz(base, rowBytes, r, kc);
}

#define CP16(dst, src)                                                          \
    asm volatile("{ .reg .u64 g; cvta.to.global.u64 g, %1;"                    \
                 " cp.async.cg.shared.global [%0], [g], 16; }"                  \
                 :: "r"(dst), "l"(src) : "memory")
#define CP_COMMIT()  asm volatile("cp.async.commit_group;" ::: "memory")
#define CP_WAITN(N)  asm volatile("cp.async.wait_group %0;" :: "n"(N) : "memory")

// ----------------------------------------------------------------- fused round
__global__ void round_all(const float* __restrict__ x,
                          const float* __restrict__ wq, const float* __restrict__ wk,
                          const float* __restrict__ wv, const float* __restrict__ wo,
                          __half* __restrict__ dx, __half* __restrict__ dw) {
    int i = blockIdx.x * 256 + threadIdx.x;          // 786432 float4 lanes
    const float4* src;
    __half* dstp;
    int off;
    if (i < 524288) {
        src = (const float4*)x; dstp = dx; off = i;
    } else {
        int j = i - 524288;
        int w = j >> 16;                             // 0..3
        off = j & 65535;
        const float* ws = (w == 0) ? wq : (w == 1) ? wk : (w == 2) ? wv : wo;
        src = (const float4*)ws;
        dstp = dw + (size_t)w * EMB * EMB;
    }
    float4 v = src[off];
    uint2 o = make_uint2(packh2(v.x, v.y), packh2(v.z, v.w));
    *((uint2*)dstp + off) = o;
}

// ----------------------------------------------------------------- GEMM core
// C[4096,512] = A[4096,512] @ B[512,512]^T, fp16 in / fp32 acc.
// BM=128 BN=64 BK=64, 256 thr. 3-stage cp.async pipeline, prefetch dist 2,
// ONE barrier per chunk (prefetch issued after barrier -> trailing sync dead).
// smem: A 3x16K + B 3x8K = 72K.
#define GSM 73728
__device__ __forceinline__ void gemm_body(const __half* A, const __half* B,
                                          void* Cout, float scale, int mode,
                                          int m0, int n0, char* sm) {
    const uint32_t sb = s2u(sm);
    const uint32_t sA[3] = {sb, sb + 16384, sb + 32768};
    const uint32_t sB[3] = {sb + 49152, sb + 57344, sb + 65536};

    const int tid = threadIdx.x, lane = tid & 31, wid = tid >> 5;
    const int wm = wid & 3, wn = wid >> 2;

    auto load = [&](int kt) {
        int buf = kt % 3;
#pragma unroll
        for (int p = 0; p < 4; p++) {
            int idx = p * 256 + tid, r = idx >> 3, kc = idx & 7;
            CP16(swz(sA[buf], 128, r, kc), &A[(size_t)(m0 + r) * EMB + kt * 64 + kc * 8]);
        }
#pragma unroll
        for (int p = 0; p < 2; p++) {
            int idx = p * 256 + tid, r = idx >> 3, kc = idx & 7;
            CP16(swz(sB[buf], 128, r, kc), &B[(size_t)(n0 + r) * EMB + kt * 64 + kc * 8]);
        }
    };

    float acc[2][4][4] = {};
    load(0); CP_COMMIT();
    load(1); CP_COMMIT();

    for (int kt = 0; kt < 8; kt++) {
        CP_WAITN(1);           // chunk kt resident (kt+1 may be in flight)
        __syncthreads();       // all warps done with buf (kt-1)%3; data visible
        if (kt + 2 < 8) load(kt + 2);   // into (kt+2)%3 == (kt-1)%3 — safe
        CP_COMMIT();
        const int b = kt % 3;
        const uint32_t a0 = sA[b], b0 = sB[b];
#pragma unroll
        for (int s = 0; s < 4; s++) {               // k16 steps
            uint32_t af[2][4], bf[2][4];
#pragma unroll
            for (int mf = 0; mf < 2; mf++)
                ldsm4(af[mf], fragAddr(a0, 128, wm * 32 + mf * 16, s * 2, lane));
#pragma unroll
            for (int p = 0; p < 2; p++)
                ldsm4(bf[p], fragAddr(b0, 128, wn * 32 + p * 16, s * 2, lane));
#pragma unroll
            for (int mf = 0; mf < 2; mf++)
#pragma unroll
                for (int p = 0; p < 2; p++) {
                    mma16(acc[mf][2 * p],     af[mf], bf[p][0], bf[p][2]);
                    mma16(acc[mf][2 * p + 1], af[mf], bf[p][1], bf[p][3]);
                }
        }
    }

#pragma unroll
    for (int mf = 0; mf < 2; mf++) {
        int r0 = m0 + wm * 32 + mf * 16 + (lane >> 2);
#pragma unroll
        for (int nf = 0; nf < 4; nf++) {
            int col = n0 + wn * 32 + nf * 8 + 2 * (lane & 3);
            float v0 = acc[mf][nf][0] * scale, v1 = acc[mf][nf][1] * scale;
            float v2 = acc[mf][nf][2] * scale, v3 = acc[mf][nf][3] * scale;
            if (mode == 0) {                         // half, row-major
                __half* C = (__half*)Cout;
                *(uint32_t*)&C[(size_t)r0 * EMB + col]       = packh2(v0, v1);
                *(uint32_t*)&C[(size_t)(r0 + 8) * EMB + col] = packh2(v2, v3);
            } else if (mode == 1) {                  // half, transposed (Vt)
                __half* C = (__half*)Cout;
                C[(size_t)col * T_SEQ + r0]           = __float2half_rn(v0);
                C[(size_t)(col + 1) * T_SEQ + r0]     = __float2half_rn(v1);
                C[(size_t)col * T_SEQ + r0 + 8]       = __float2half_rn(v2);
                C[(size_t)(col + 1) * T_SEQ + r0 + 8] = __float2half_rn(v3);
            } else {                                 // fp32 final output
                float* C = (float*)Cout;
                *(float2*)&C[(size_t)r0 * EMB + col]       = make_float2(v0, v1);
                *(float2*)&C[(size_t)(r0 + 8) * EMB + col] = make_float2(v2, v3);
            }
        }
    }
}

// Fused QKV: blockIdx.x: [0,8) -> Q, [8,16) -> K, [16,24) -> V(transposed out)
__global__ __launch_bounds__(256, 2) void qkv_gemm(const __half* __restrict__ A,
                                                   const __half* __restrict__ W,
                                                   __half* __restrict__ Cq,
                                                   __half* __restrict__ Ck,
                                                   __half* __restrict__ Cv) {
    extern __shared__ __align__(1024) char sm[];
    int which = blockIdx.x >> 3;
    int n0 = (blockIdx.x & 7) * 64;
    int m0 = blockIdx.y * 128;
    const __half* B = W + (size_t)which * EMB * EMB;
    __half* C = (which == 0) ? Cq : (which == 1) ? Ck : Cv;
    float scale = (which == 0) ? QSCALE : 1.0f;
    gemm_body(A, B, C, scale, (which == 2) ? 1 : 0, m0, n0, sm);
}

__global__ __launch_bounds__(256, 2) void gemm_out(const __half* __restrict__ A,
                                                   const __half* __restrict__ B,
                                                   float* __restrict__ C) {
    extern __shared__ __align__(1024) char sm[];
    gemm_body(A, B, C, 1.0f, 2, blockIdx.y * 128, blockIdx.x * 64, sm);
}

// ----------------------------------------------------------------- attention
// CTA: 128 q x 1 head, 64 key tiles of 64 keys, 256 thr, 2 CTAs/SM.
// Warp owns 16 q-rows across ALL keys. exp via ex2.approx.f16x2 (output =
// packed fp16 A-frag). l = P x ones via one extra MMA per k16 chunk.
// K/V triple-buffered; prefetch issued AFTER the barrier -> ONE barrier/tile.
// smem: Q 16K | K 3x8K | V 3x8K = 64K.
#define ASMEM 65536
#define ONESH2 0x3C003C00u
__global__ __launch_bounds__(256, 2) void attn_tc(const __half* __restrict__ Q,
                                                  const __half* __restrict__ K,
                                                  const __half* __restrict__ Vt,
                                                  __half* __restrict__ O) {
    extern __shared__ __align__(1024) char sm[];
    const uint32_t sb = s2u(sm);
    const uint32_t sQ = sb;
    const uint32_t sK[3] = {sb + 16384, sb + 24576, sb + 32768};
    const uint32_t sV[3] = {sb + 40960, sb + 49152, sb + 57344};

    const int tid = threadIdx.x, lane = tid & 31, wid = tid >> 5;
    const int h = blockIdx.y, q0 = blockIdx.x * 128;

    auto loadKV = [&](int t, int buf) {
        int k0 = t * 64;
#pragma unroll
        for (int p = 0; p < 2; p++) {
            int idx = p * 256 + tid, r = idx >> 3, kc = idx & 7;
            CP16(swz(sK[buf], 128, r, kc), &K[(size_t)(k0 + r) * EMB + h * HDIM + kc * 8]);
            CP16(swz(sV[buf], 128, r, kc), &Vt[(size_t)(h * HDIM + r) * T_SEQ + k0 + kc * 8]);
        }
    };

    // prologue: group0 = {Q, K0, V0}, group1 = {K1, V1}
#pragma unroll
    for (int p = 0; p < 4; p++) {
        int idx = p * 256 + tid, r = idx >> 3, kc = idx & 7;
        CP16(swz(sQ, 128, r, kc), &Q[(size_t)(q0 + r) * EMB + h * HDIM + kc * 8]);
    }
    loadKV(0, 0); CP_COMMIT();
    loadKV(1, 1); CP_COMMIT();
    CP_WAITN(1);               // Q, K0, V0 resident
    __syncthreads();

    // register-cache Q fragments: m16 x k64 per warp = 16 regs
    uint32_t qf[4][4];
#pragma unroll
    for (int s = 0; s < 4; s++)
        ldsm4(qf[s], fragAddr(sQ, 128, wid * 16, s * 2, lane));

    float oacc[8][4] = {};
    float lacc[4] = {};

    int buf = 0;               // buffer of tile t (t % 3)
    for (int t = 0; t < 64; t++) {
        if (t > 0) {
            CP_WAITN(1);       // tile t resident (t+1 may be in flight)
            __syncthreads();   // all warps done with buf (t-1)%3; data visible
        }
        if (t + 2 < 64) {      // prefetch into (t+2)%3 == (t-1)%3 — safe
            int pb = buf + 2; if (pb >= 3) pb -= 3;
            loadKV(t + 2, pb);
        }
        CP_COMMIT();

        // --- S = Q K(t)^T over all 64 keys (log2 domain) ---
        float sacc[8][4] = {};
        const uint32_t kb = sK[buf];
#pragma unroll
        for (int s = 0; s < 4; s++) {
            uint32_t kf[4][4];
#pragma unroll
            for (int nb = 0; nb < 4; nb++)
                ldsm4(kf[nb], fragAddr(kb, 128, nb * 16, s * 2, lane));
#pragma unroll
            for (int nb = 0; nb < 4; nb++) {
                mma16(sacc[2 * nb],     qf[s], kf[nb][0], kf[nb][2]);
                mma16(sacc[2 * nb + 1], qf[s], kf[nb][1], kf[nb][3]);
            }
        }

        // --- P = 2^S via f16x2 MUFU (output = packed A-frag); l via ones-MMA ---
        uint32_t aP[4][4];
#pragma unroll
        for (int nf = 0; nf < 8; nf++) {
            uint32_t e01 = ex2h2(packh2(sacc[nf][0], sacc[nf][1]));
            uint32_t e23 = ex2h2(packh2(sacc[nf][2], sacc[nf][3]));
            int ks = nf >> 1, hi = (nf & 1) * 2;
            aP[ks][hi]     = e01;
            aP[ks][hi + 1] = e23;
        }
#pragma unroll
        for (int ks = 0; ks < 4; ks++)
            mma16(lacc, aP[ks], ONESH2, ONESH2);

        // --- O += P V(t) over all 64 keys ---
        const uint32_t vb = sV[buf];
#pragma unroll
        for (int ks = 0; ks < 4; ks++) {
            uint32_t bf[4][4];
#pragma unroll
            for (int p = 0; p < 4; p++)
                ldsm4(bf[p], fragAddr(vb, 128, p * 16, ks * 2, lane));
#pragma unroll
            for (int p = 0; p < 4; p++) {
                mma16(oacc[2 * p],     aP[ks], bf[p][0], bf[p][2]);
                mma16(oacc[2 * p + 1], aP[ks], bf[p][1], bf[p][3]);
            }
        }
        buf++; if (buf >= 3) buf = 0;
    }

    // --- O /= l (l from ones-MMA: rows r / r+8 in lacc[0] / lacc[2]) ---
    float li0 = 1.0f / lacc[0];
    float li1 = 1.0f / lacc[2];
    int r = wid * 16 + (lane >> 2);
#pragma unroll
    for (int df = 0; df < 8; df++) {
        int col = df * 8 + 2 * (lane & 3);
        *(uint32_t*)&O[(size_t)(q0 + r) * EMB + h * HDIM + col] =
            packh2(oacc[df][0] * li0, oacc[df][1] * li0);
        *(uint32_t*)&O[(size_t)(q0 + r + 8) * EMB + h * HDIM + col] =
            packh2(oacc[df][2] * li1, oacc[df][3] * li1);
    }
}

// ----------------------------------------------------------------- launch
extern "C" void kernel_launch(void* const* d_in, const int* in_sizes, int n_in,
                              void* d_out, int out_size) {
    const float* x  = (const float*)d_in[0];
    const float* wq = (const float*)d_in[1];
    const float* wk = (const float*)d_in[2];
    const float* wv = (const float*)d_in[3];
    const float* wo = (const float*)d_in[4];
    float* out = (float*)d_out;

    __half *px, *pw, *pQ, *pK, *pVt, *pA;
    cudaGetSymbolAddress((void**)&px, g_x);
    cudaGetSymbolAddress((void**)&pw, g_w);
    cudaGetSymbolAddress((void**)&pQ, g_Q);
    cudaGetSymbolAddress((void**)&pK, g_K);
    cudaGetSymbolAddress((void**)&pVt, g_Vt);
    cudaGetSymbolAddress((void**)&pA, g_att);

    cudaFuncSetAttribute(qkv_gemm, cudaFuncAttributeMaxDynamicSharedMemorySize, GSM);
    cudaFuncSetAttribute(gemm_out, cudaFuncAttributeMaxDynamicSharedMemorySize, GSM);
    cudaFuncSetAttribute(attn_tc, cudaFuncAttributeMaxDynamicSharedMemorySize, ASMEM);

    round_all<<<3072, 256>>>(x, wq, wk, wv, wo, px, pw);

    qkv_gemm<<<dim3(24, 32), 256, GSM>>>(px, pw, pQ, pK, pVt);

    dim3 ga(T_SEQ / 128, NHEAD);       // (32, 8) = 256 CTAs, one wave @2/SM
    attn_tc<<<ga, 256, ASMEM>>>(pQ, pK, pVt, pA);

    gemm_out<<<dim3(8, 32), 256, GSM>>>(pA, pw + 3 * (size_t)EMB * EMB, out);
}

// round 12
// speedup vs baseline: 1.0404x; 1.0165x over previous
#include <cuda_runtime.h>
#include <cuda_fp16.h>
#include <math.h>
#include <stdint.h>

#define T_SEQ 4096
#define EMB   512
#define NHEAD 8
#define HDIM  64
#define QSCALE 0.18033688011112042f   // (1/8) * log2(e): softmax via ex2

// Scratch (allocation-free rule) — all fp16 intermediates
__device__ __align__(1024) __half g_x [T_SEQ * EMB];
__device__ __align__(1024) __half g_w [4 * EMB * EMB];
__device__ __align__(1024) __half g_Q [T_SEQ * EMB];
__device__ __align__(1024) __half g_K [T_SEQ * EMB];
__device__ __align__(1024) __half g_Vt[EMB * T_SEQ];   // [n=h*64+d][t]
__device__ __align__(1024) __half g_att[T_SEQ * EMB];

// ----------------------------------------------------------------- helpers
__device__ __forceinline__ uint32_t s2u(const void* p) {
    uint32_t a;
    asm("{ .reg .u64 t; cvta.to.shared.u64 t, %1; cvt.u32.u64 %0, t; }"
        : "=r"(a) : "l"(p));
    return a;
}
__device__ __forceinline__ uint32_t packh2(float lo, float hi) {
    __half2 h = __floats2half2_rn(lo, hi);
    return *(uint32_t*)&h;
}
__device__ __forceinline__ uint32_t ex2h2(uint32_t x) {
    uint32_t y;
    asm("ex2.approx.f16x2 %0, %1;" : "=r"(y) : "r"(x));
    return y;
}
__device__ __forceinline__ void ldsm4(uint32_t* r, uint32_t addr) {
    asm volatile("ldmatrix.sync.aligned.m8n8.x4.shared.b16 {%0,%1,%2,%3}, [%4];"
                 : "=r"(r[0]), "=r"(r[1]), "=r"(r[2]), "=r"(r[3]) : "r"(addr));
}
__device__ __forceinline__ void mma16(float* c, const uint32_t* a,
                                      uint32_t b0, uint32_t b1) {
    asm volatile(
        "mma.sync.aligned.m16n8k16.row.col.f32.f16.f16.f32 "
        "{%0,%1,%2,%3}, {%4,%5,%6,%7}, {%8,%9}, {%0,%1,%2,%3};"
        : "+f"(c[0]), "+f"(c[1]), "+f"(c[2]), "+f"(c[3])
        : "r"(a[0]), "r"(a[1]), "r"(a[2]), "r"(a[3]), "r"(b0), "r"(b1));
}
// 16B-chunk XOR swizzle (8 chunks per 128B row of 64 halves)
__device__ __forceinline__ uint32_t swz(uint32_t base, int rowBytes, int r, int kc) {
    return base + (uint32_t)r * rowBytes + ((uint32_t)(kc ^ (r & 7)) << 4);
}
__device__ __forceinline__ uint32_t fragAddr(uint32_t base, int rowBytes,
                                             int r0, int kc0, int lane) {
    int r  = r0 + (lane & 7) + ((lane >> 3) & 1) * 8;
    int kc = kc0 + (lane >> 4);
    return swz(base, rowBytes, r, kc);
}

#define CP16(dst, src)                                                          \
    asm volatile("{ .reg .u64 g; cvta.to.global.u64 g, %1;"                    \
                 " cp.async.cg.shared.global [%0], [g], 16; }"                  \
                 :: "r"(dst), "l"(src) : "memory")
#define CP_COMMIT()  asm volatile("cp.async.commit_group;" ::: "memory")
#define CP_WAITN(N)  asm volatile("cp.async.wait_group %0;" :: "n"(N) : "memory")

// ----------------------------------------------------------------- fused round
__global__ void round_all(const float* __restrict__ x,
                          const float* __restrict__ wq, const float* __restrict__ wk,
                          const float* __restrict__ wv, const float* __restrict__ wo,
                          __half* __restrict__ dx, __half* __restrict__ dw) {
    int i = blockIdx.x * 256 + threadIdx.x;          // 786432 float4 lanes
    const float4* src;
    __half* dstp;
    int off;
    if (i < 524288) {
        src = (const float4*)x; dstp = dx; off = i;
    } else {
        int j = i - 524288;
        int w = j >> 16;                             // 0..3
        off = j & 65535;
        const float* ws = (w == 0) ? wq : (w == 1) ? wk : (w == 2) ? wv : wo;
        src = (const float4*)ws;
        dstp = dw + (size_t)w * EMB * EMB;
    }
    float4 v = src[off];
    uint2 o = make_uint2(packh2(v.x, v.y), packh2(v.z, v.w));
    *((uint2*)dstp + off) = o;
}

// ----------------------------------------------------------------- GEMM core
// C[4096,512] = A[4096,512] @ B[512,512]^T, fp16 in / fp32 acc.
// BM=128 BN=64 BK=64, 256 thr. 3-stage cp.async pipeline, prefetch dist 2,
// ONE barrier per chunk. smem: A 3x16K + B 3x8K = 72K.
#define GSM 73728
__device__ __forceinline__ void gemm_body(const __half* A, const __half* B,
                                          void* Cout, float scale, int mode,
                                          int m0, int n0, char* sm) {
    const uint32_t sb = s2u(sm);
    const uint32_t sA[3] = {sb, sb + 16384, sb + 32768};
    const uint32_t sB[3] = {sb + 49152, sb + 57344, sb + 65536};

    const int tid = threadIdx.x, lane = tid & 31, wid = tid >> 5;
    const int wm = wid & 3, wn = wid >> 2;

    auto load = [&](int kt) {
        int buf = kt % 3;
#pragma unroll
        for (int p = 0; p < 4; p++) {
            int idx = p * 256 + tid, r = idx >> 3, kc = idx & 7;
            CP16(swz(sA[buf], 128, r, kc), &A[(size_t)(m0 + r) * EMB + kt * 64 + kc * 8]);
        }
#pragma unroll
        for (int p = 0; p < 2; p++) {
            int idx = p * 256 + tid, r = idx >> 3, kc = idx & 7;
            CP16(swz(sB[buf], 128, r, kc), &B[(size_t)(n0 + r) * EMB + kt * 64 + kc * 8]);
        }
    };

    float acc[2][4][4] = {};
    load(0); CP_COMMIT();
    load(1); CP_COMMIT();

    for (int kt = 0; kt < 8; kt++) {
        CP_WAITN(1);           // chunk kt resident (kt+1 may be in flight)
        __syncthreads();       // all warps done with buf (kt-1)%3; data visible
        if (kt + 2 < 8) load(kt + 2);   // into (kt+2)%3 == (kt-1)%3 — safe
        CP_COMMIT();
        const int b = kt % 3;
        const uint32_t a0 = sA[b], b0 = sB[b];
#pragma unroll
        for (int s = 0; s < 4; s++) {               // k16 steps
            uint32_t af[2][4], bf[2][4];
#pragma unroll
            for (int mf = 0; mf < 2; mf++)
                ldsm4(af[mf], fragAddr(a0, 128, wm * 32 + mf * 16, s * 2, lane));
#pragma unroll
            for (int p = 0; p < 2; p++)
                ldsm4(bf[p], fragAddr(b0, 128, wn * 32 + p * 16, s * 2, lane));
#pragma unroll
            for (int mf = 0; mf < 2; mf++)
#pragma unroll
                for (int p = 0; p < 2; p++) {
                    mma16(acc[mf][2 * p],     af[mf], bf[p][0], bf[p][2]);
                    mma16(acc[mf][2 * p + 1], af[mf], bf[p][1], bf[p][3]);
                }
        }
    }

#pragma unroll
    for (int mf = 0; mf < 2; mf++) {
        int r0 = m0 + wm * 32 + mf * 16 + (lane >> 2);
#pragma unroll
        for (int nf = 0; nf < 4; nf++) {
            int col = n0 + wn * 32 + nf * 8 + 2 * (lane & 3);
            float v0 = acc[mf][nf][0] * scale, v1 = acc[mf][nf][1] * scale;
            float v2 = acc[mf][nf][2] * scale, v3 = acc[mf][nf][3] * scale;
            if (mode == 0) {                         // half, row-major
                __half* C = (__half*)Cout;
                *(uint32_t*)&C[(size_t)r0 * EMB + col]       = packh2(v0, v1);
                *(uint32_t*)&C[(size_t)(r0 + 8) * EMB + col] = packh2(v2, v3);
            } else if (mode == 1) {                  // half, transposed (Vt)
                __half* C = (__half*)Cout;
                C[(size_t)col * T_SEQ + r0]           = __float2half_rn(v0);
                C[(size_t)(col + 1) * T_SEQ + r0]     = __float2half_rn(v1);
                C[(size_t)col * T_SEQ + r0 + 8]       = __float2half_rn(v2);
                C[(size_t)(col + 1) * T_SEQ + r0 + 8] = __float2half_rn(v3);
            } else {                                 // fp32 final output
                float* C = (float*)Cout;
                *(float2*)&C[(size_t)r0 * EMB + col]       = make_float2(v0, v1);
                *(float2*)&C[(size_t)(r0 + 8) * EMB + col] = make_float2(v2, v3);
            }
        }
    }
}

// Fused QKV: blockIdx.x: [0,8) -> Q, [8,16) -> K, [16,24) -> V(transposed out)
__global__ __launch_bounds__(256, 2) void qkv_gemm(const __half* __restrict__ A,
                                                   const __half* __restrict__ W,
                                                   __half* __restrict__ Cq,
                                                   __half* __restrict__ Ck,
                                                   __half* __restrict__ Cv) {
    extern __shared__ __align__(1024) char sm[];
    int which = blockIdx.x >> 3;
    int n0 = (blockIdx.x & 7) * 64;
    int m0 = blockIdx.y * 128;
    const __half* B = W + (size_t)which * EMB * EMB;
    __half* C = (which == 0) ? Cq : (which == 1) ? Ck : Cv;
    float scale = (which == 0) ? QSCALE : 1.0f;
    gemm_body(A, B, C, scale, (which == 2) ? 1 : 0, m0, n0, sm);
}

__global__ __launch_bounds__(256, 2) void gemm_out(const __half* __restrict__ A,
                                                   const __half* __restrict__ B,
                                                   float* __restrict__ C) {
    extern __shared__ __align__(1024) char sm[];
    gemm_body(A, B, C, 1.0f, 2, blockIdx.y * 128, blockIdx.x * 64, sm);
}

// ----------------------------------------------------------------- attention
// CTA: 128 q x 1 head, 4 warps of m32 (halves LDSM broadcast redundancy vs
// 8 x m16), 128 thr, 2 CTAs/SM. 64 key tiles of 64 keys. exp via
// ex2.approx.f16x2 (output = packed fp16 A-frag); l = P x ones MMA.
// S computed per-m16-half sequentially to cap register peak (~205).
// K/V triple-buffered; ONE barrier/tile. smem: Q 16K | K 3x8K | V 3x8K = 64K.
#define ASMEM 65536
#define ONESH2 0x3C003C00u
__global__ __launch_bounds__(128, 2) void attn_tc(const __half* __restrict__ Q,
                                                  const __half* __restrict__ K,
                                                  const __half* __restrict__ Vt,
                                                  __half* __restrict__ O) {
    extern __shared__ __align__(1024) char sm[];
    const uint32_t sb = s2u(sm);
    const uint32_t sQ = sb;
    const uint32_t sK[3] = {sb + 16384, sb + 24576, sb + 32768};
    const uint32_t sV[3] = {sb + 40960, sb + 49152, sb + 57344};

    const int tid = threadIdx.x, lane = tid & 31, wid = tid >> 5;  // 4 warps
    const int h = blockIdx.y, q0 = blockIdx.x * 128;

    auto loadKV = [&](int t, int buf) {
        int k0 = t * 64;
#pragma unroll
        for (int p = 0; p < 4; p++) {
            int idx = p * 128 + tid, r = idx >> 3, kc = idx & 7;
            CP16(swz(sK[buf], 128, r, kc), &K[(size_t)(k0 + r) * EMB + h * HDIM + kc * 8]);
            CP16(swz(sV[buf], 128, r, kc), &Vt[(size_t)(h * HDIM + r) * T_SEQ + k0 + kc * 8]);
        }
    };

    // prologue: group0 = {Q, K0, V0}, group1 = {K1, V1}
#pragma unroll
    for (int p = 0; p < 8; p++) {
        int idx = p * 128 + tid, r = idx >> 3, kc = idx & 7;
        CP16(swz(sQ, 128, r, kc), &Q[(size_t)(q0 + r) * EMB + h * HDIM + kc * 8]);
    }
    loadKV(0, 0); CP_COMMIT();
    loadKV(1, 1); CP_COMMIT();
    CP_WAITN(1);               // Q, K0, V0 resident
    __syncthreads();

    // register-cache Q fragments: m32 x k64 per warp = 32 regs
    uint32_t qf[4][2][4];
#pragma unroll
    for (int s = 0; s < 4; s++)
#pragma unroll
        for (int mf = 0; mf < 2; mf++)
            ldsm4(qf[s][mf], fragAddr(sQ, 128, wid * 32 + mf * 16, s * 2, lane));

    float oacc[2][8][4] = {};
    float lacc[2][4] = {};

    int buf = 0;               // buffer of tile t (t % 3)
    for (int t = 0; t < 64; t++) {
        if (t > 0) {
            CP_WAITN(1);       // tile t resident (t+1 may be in flight)
            __syncthreads();   // all warps done with buf (t-1)%3; data visible
        }
        if (t + 2 < 64) {      // prefetch into (t+2)%3 == (t-1)%3 — safe
            int pb = buf + 2; if (pb >= 3) pb -= 3;
            loadKV(t + 2, pb);
        }
        CP_COMMIT();

        const uint32_t kb = sK[buf];
        const uint32_t vb = sV[buf];
        uint32_t aP[2][4][4];

        // --- per m16 half: S = Q K(t)^T, then P = 2^S, l += P*1 ---
#pragma unroll
        for (int mf = 0; mf < 2; mf++) {
            float sacc[8][4] = {};
#pragma unroll
            for (int s = 0; s < 4; s++) {
                uint32_t kf[4][4];
#pragma unroll
                for (int nb = 0; nb < 4; nb++)
                    ldsm4(kf[nb], fragAddr(kb, 128, nb * 16, s * 2, lane));
#pragma unroll
                for (int nb = 0; nb < 4; nb++) {
                    mma16(sacc[2 * nb],     qf[s][mf], kf[nb][0], kf[nb][2]);
                    mma16(sacc[2 * nb + 1], qf[s][mf], kf[nb][1], kf[nb][3]);
                }
            }
#pragma unroll
            for (int nf = 0; nf < 8; nf++) {
                uint32_t e01 = ex2h2(packh2(sacc[nf][0], sacc[nf][1]));
                uint32_t e23 = ex2h2(packh2(sacc[nf][2], sacc[nf][3]));
                int ks = nf >> 1, hi = (nf & 1) * 2;
                aP[mf][ks][hi]     = e01;
                aP[mf][ks][hi + 1] = e23;
            }
#pragma unroll
            for (int ks = 0; ks < 4; ks++)
                mma16(lacc[mf], aP[mf][ks], ONESH2, ONESH2);
        }

        // --- O += P V(t): share each V fragment across both m16 halves ---
#pragma unroll
        for (int ks = 0; ks < 4; ks++) {
            uint32_t bf[4][4];
#pragma unroll
            for (int p = 0; p < 4; p++)
                ldsm4(bf[p], fragAddr(vb, 128, p * 16, ks * 2, lane));
#pragma unroll
            for (int mf = 0; mf < 2; mf++)
#pragma unroll
                for (int p = 0; p < 4; p++) {
                    mma16(oacc[mf][2 * p],     aP[mf][ks], bf[p][0], bf[p][2]);
                    mma16(oacc[mf][2 * p + 1], aP[mf][ks], bf[p][1], bf[p][3]);
                }
        }
        buf++; if (buf >= 3) buf = 0;
    }

    // --- O /= l (l rows r / r+8 in lacc[mf][0] / lacc[mf][2]) ---
#pragma unroll
    for (int mf = 0; mf < 2; mf++) {
        float li0 = 1.0f / lacc[mf][0];
        float li1 = 1.0f / lacc[mf][2];
        int r = wid * 32 + mf * 16 + (lane >> 2);
#pragma unroll
        for (int df = 0; df < 8; df++) {
            int col = df * 8 + 2 * (lane & 3);
            *(uint32_t*)&O[(size_t)(q0 + r) * EMB + h * HDIM + col] =
                packh2(oacc[mf][df][0] * li0, oacc[mf][df][1] * li0);
            *(uint32_t*)&O[(size_t)(q0 + r + 8) * EMB + h * HDIM + col] =
                packh2(oacc[mf][df][2] * li1, oacc[mf][df][3] * li1);
        }
    }
}

// ----------------------------------------------------------------- launch
extern "C" void kernel_launch(void* const* d_in, const int* in_sizes, int n_in,
                              void* d_out, int out_size) {
    const float* x  = (const float*)d_in[0];
    const float* wq = (const float*)d_in[1];
    const float* wk = (const float*)d_in[2];
    const float* wv = (const float*)d_in[3];
    const float* wo = (const float*)d_in[4];
    float* out = (float*)d_out;

    __half *px, *pw, *pQ, *pK, *pVt, *pA;
    cudaGetSymbolAddress((void**)&px, g_x);
    cudaGetSymbolAddress((void**)&pw, g_w);
    cudaGetSymbolAddress((void**)&pQ, g_Q);
    cudaGetSymbolAddress((void**)&pK, g_K);
    cudaGetSymbolAddress((void**)&pVt, g_Vt);
    cudaGetSymbolAddress((void**)&pA, g_att);

    cudaFuncSetAttribute(qkv_gemm, cudaFuncAttributeMaxDynamicSharedMemorySize, GSM);
    cudaFuncSetAttribute(gemm_out, cudaFuncAttributeMaxDynamicSharedMemorySize, GSM);
    cudaFuncSetAttribute(attn_tc, cudaFuncAttributeMaxDynamicSharedMemorySize, ASMEM);

    round_all<<<3072, 256>>>(x, wq, wk, wv, wo, px, pw);

    qkv_gemm<<<dim3(24, 32), 256, GSM>>>(px, pw, pQ, pK, pVt);

    dim3 ga(T_SEQ / 128, NHEAD);       // (32, 8) = 256 CTAs of 128 thr, 2/SM
    attn_tc<<<ga, 128, ASMEM>>>(pQ, pK, pVt, pA);

    gemm_out<<<dim3(8, 32), 256, GSM>>>(pA, pw + 3 * (size_t)EMB * EMB, out);
}